// round 7
// baseline (speedup 1.0000x reference)
#include <cuda_runtime.h>
#include <cuda_fp16.h>
#include <math.h>
#include <stdint.h>

#define BB   64
#define TT   512
#define DD   512
#define UU   1024
#define G4   4096
#define NCTA 128

__device__ float  g_xg[(size_t)BB * TT * G4];                 // [t][b][4096]
__device__ __align__(16) __half g_xh[(size_t)BB * TT * DD];
__device__ __align__(16) __half g_hh[2][BB * UU];
__device__ volatile unsigned g_bar_gen = 0;
__device__ unsigned g_root_cnt = 0;
__device__ unsigned g_grp_cnt[16 * 32];                       // 128B-strided counters

__device__ __forceinline__ void mma16(float c[4], unsigned a0, unsigned a1,
                                      unsigned a2, unsigned a3,
                                      unsigned b0, unsigned b1) {
    asm volatile(
        "mma.sync.aligned.m16n8k16.row.col.f32.f16.f16.f32 "
        "{%0,%1,%2,%3}, {%4,%5,%6,%7}, {%8,%9}, {%0,%1,%2,%3};"
        : "+f"(c[0]), "+f"(c[1]), "+f"(c[2]), "+f"(c[3])
        : "r"(a0), "r"(a1), "r"(a2), "r"(a3), "r"(b0), "r"(b1));
}
__device__ __forceinline__ uint4 ldsm4(unsigned addr) {
    uint4 r;
    asm volatile("ldmatrix.sync.aligned.m8n8.x4.shared.b16 {%0,%1,%2,%3}, [%4];"
                 : "=r"(r.x), "=r"(r.y), "=r"(r.z), "=r"(r.w) : "r"(addr));
    return r;
}
__device__ __forceinline__ void cp16(unsigned dst, const void* src) {
    asm volatile("cp.async.cg.shared.global [%0], [%1], 16;" :: "r"(dst), "l"(src));
}
__device__ __forceinline__ float sigmoidf_(float x) { return 1.0f / (1.0f + expf(-x)); }
__device__ __forceinline__ unsigned smem_u32(const void* p) {
    unsigned a;
    asm("{ .reg .u64 t; cvta.to.shared.u64 t, %1; cvt.u32.u64 %0, t; }" : "=r"(a) : "l"(p));
    return a;
}
__device__ __forceinline__ int slot_perm(int slot5) {
    int s = slot5 >> 4, p = slot5 & 15;
    int lcp = (p < 8) ? (p >> 1) : ((p - 8) >> 1);
    int add = (p < 8) ? 0 : 2;
    return 8 * lcp + 4 * s + add + (p & 1);
}

// ---- tree grid barrier (16 groups x 8 CTAs; single-gen release) ----
__device__ __forceinline__ void bar_arrive(int bid, unsigned& gen) {
    gen = g_bar_gen;
    __threadfence();                                   // release prior writes
    if (atomicAdd(&g_grp_cnt[(bid >> 3) * 32], 1u) == 7u) {
        g_grp_cnt[(bid >> 3) * 32] = 0u;
        __threadfence();
        if (atomicAdd(&g_root_cnt, 1u) == 15u) {
            g_root_cnt = 0u;
            __threadfence();
            g_bar_gen = gen + 1u;
        }
    }
}
__device__ __forceinline__ void bar_wait(unsigned gen) {
    while (g_bar_gen == gen) { __nanosleep(32); }
    __threadfence();                                   // acquire
}

// ========================== conv_x ==========================
__global__ __launch_bounds__(256) void conv_x(const float* __restrict__ x) {
    const size_t n4 = (size_t)BB * TT * DD / 4;
    for (size_t i = (size_t)blockIdx.x * 256 + threadIdx.x; i < n4;
         i += (size_t)gridDim.x * 256) {
        float4 v = reinterpret_cast<const float4*>(x)[i];
        __half2 h01 = __floats2half2_rn(v.x, v.y);
        __half2 h23 = __floats2half2_rn(v.z, v.w);
        uint2 st;
        st.x = *reinterpret_cast<unsigned*>(&h01);
        st.y = *reinterpret_cast<unsigned*>(&h23);
        reinterpret_cast<uint2*>(g_xh)[i] = st;
    }
}

// ========================== xg_kernel (validated, unchanged) ==========================
#define XG_WT_STRIDE 520
__global__ __launch_bounds__(256) void xg_kernel(
    const float* __restrict__ Wx, const float* __restrict__ bias)
{
    __shared__ __half Wt[32 * XG_WT_STRIDE];
    const int tid = threadIdx.x, warp = tid >> 5, lane = tid & 31;
    const int lr = lane >> 2, lc = lane & 3;
    const int mo = (warp & 3) * 16, no = (warp >> 2) * 16;
    const int ns = blockIdx.x & 127, mg = blockIdx.x >> 7, u0 = ns * 8;

    for (int i = tid; i < 32 * 512; i += 256) {
        int n = i & 31, slotg = i >> 5;
        int k = (slotg & ~31) + slot_perm(slotg & 31);
        int col = (n >> 3) * UU + u0 + (n & 7);
        Wt[n * XG_WT_STRIDE + slotg] = __float2half_rn(Wx[(size_t)k * G4 + col]);
    }
    __syncthreads();
    const unsigned WtB = smem_u32(Wt);
    const unsigned bAddrBase = WtB
        + (unsigned)(no + ((lane >> 4) << 3) + (lane & 7)) * (XG_WT_STRIDE * 2)
        + ((lane >> 3) & 1) * 16;
    float bv[2][2];
#pragma unroll
    for (int j = 0; j < 2; j++) {
        int cl = no + j * 8 + 2 * lc;
        int colg = (cl >> 3) * UU + u0 + (cl & 7);
        bv[j][0] = bias[colg]; bv[j][1] = bias[colg + 1];
    }
    for (int mt = 0; mt < 64; mt++) {
        const int r0 = mg * 4096 + mt * 64;
        const __half* pr0 = g_xh + (size_t)(r0 + mo + lr) * DD + 8 * lc;
        const __half* pr1 = pr0 + 8 * DD;
        float acc[2][4];
#pragma unroll
        for (int j = 0; j < 2; j++)
#pragma unroll
            for (int i = 0; i < 4; i++) acc[j][i] = 0.0f;
        uint4 a0c = *reinterpret_cast<const uint4*>(pr0);
        uint4 a1c = *reinterpret_cast<const uint4*>(pr1);
        uint4 a0n = *reinterpret_cast<const uint4*>(pr0 + 32);
        uint4 a1n = *reinterpret_cast<const uint4*>(pr1 + 32);
#pragma unroll
        for (int kc = 0; kc < 16; kc++) {
            uint4 a0f = make_uint4(0, 0, 0, 0), a1f = a0f;
            if (kc < 14) {
                a0f = *reinterpret_cast<const uint4*>(pr0 + (kc + 2) * 32);
                a1f = *reinterpret_cast<const uint4*>(pr1 + (kc + 2) * 32);
            }
            const unsigned ba = bAddrBase + kc * 64;
            uint4 B0 = ldsm4(ba);
            uint4 B1 = ldsm4(ba + 32);
            mma16(acc[0], a0c.x, a1c.x, a0c.y, a1c.y, B0.x, B0.y);
            mma16(acc[1], a0c.x, a1c.x, a0c.y, a1c.y, B0.z, B0.w);
            mma16(acc[0], a0c.z, a1c.z, a0c.w, a1c.w, B1.x, B1.y);
            mma16(acc[1], a0c.z, a1c.z, a0c.w, a1c.w, B1.z, B1.w);
            a0c = a0n; a1c = a1n; a0n = a0f; a1n = a1f;
        }
        const int rA = r0 + mo + lr, rB = rA + 8;
        const size_t row0 = (size_t)((rA & (TT - 1)) * BB + (rA >> 9)) * G4;
        const size_t row1 = (size_t)((rB & (TT - 1)) * BB + (rB >> 9)) * G4;
#pragma unroll
        for (int j = 0; j < 2; j++) {
            int cl = no + j * 8 + 2 * lc;
            int colg = (cl >> 3) * UU + u0 + (cl & 7);
            *reinterpret_cast<float2*>(&g_xg[row0 + colg]) =
                make_float2(acc[j][0] + bv[j][0], acc[j][1] + bv[j][1]);
            *reinterpret_cast<float2*>(&g_xg[row1 + colg]) =
                make_float2(acc[j][2] + bv[j][0], acc[j][3] + bv[j][1]);
        }
    }
}

// ================= persistent K-split LSTM step kernel =================
// Warp w owns K-slice [128w, 128w+128): stages its own h slice, computes
// partial gates[64][32] over its K range, stores partials over its (dead)
// A slice, CTA reduces 8 partials fused with the cell update.
#define A_STRIDE   136                       // fp16 per A row (128 + 8 pad)
#define A_SLICE_B  (64 * A_STRIDE * 2)       // 17408 B per warp slice
#define A_SLICE_F  (A_SLICE_B / 4)           // 4352 floats
#define P_STRIDE   33                        // partial floats per row
#define WT_STRIDE  1032                      // fp16 per Wt n-row
#define SM_W   (8 * A_SLICE_B)               // 139264
#define SM_CL  (SM_W + 32 * WT_STRIDE * 2)   // 205312
#define SMEM_BYTES (SM_CL + 2048 + 128)

__global__ __launch_bounds__(256) void lstm_persist(
    const float* __restrict__ Wh, const float* __restrict__ h0,
    const float* __restrict__ c0, float* __restrict__ out)
{
    extern __shared__ char sm[];
    __half* Wt  = (__half*)(sm + SM_W);
    float*  Cl  = (float*)(sm + SM_CL);
    float*  Pal = (float*)sm;                 // partial overlay of A region

    const int tid = threadIdx.x, warp = tid >> 5, lane = tid & 31;
    const int lr = lane >> 2, lc = lane & 3;
    const int u0 = blockIdx.x * 8;
    const int bid = blockIdx.x;
    const unsigned smB = smem_u32(sm);

    // ---- one-time init ----
    for (int i = tid; i < 32 * 1024; i += 256) {
        int n = i & 31, k = i >> 5;
        int col = (n >> 3) * UU + u0 + (n & 7);
        Wt[n * WT_STRIDE + k] = __float2half_rn(Wh[(size_t)k * G4 + col]);
    }
    for (int i = tid; i < 512; i += 256)
        Cl[i] = c0[(i >> 3) * UU + u0 + (i & 7)];
    for (int i = bid * 256 + tid; i < BB * UU; i += NCTA * 256)
        g_hh[0][i] = __float2half_rn(h0[i]);
    __syncthreads();
    {
        unsigned gen;
        if (tid == 0) bar_arrive(bid, gen);
        if (tid == 0) bar_wait(gen);
        __syncthreads();
    }

    const unsigned AwB = smB + warp * A_SLICE_B;
    const unsigned WtB = smB + SM_W;
    const int wk0 = warp * 128;                            // k offset of slice

    // ldmatrix lane bases
    const unsigned aLane = (unsigned)((lane & 15) * (A_STRIDE * 2) + (lane >> 4) * 16);
    const unsigned bRow  = (unsigned)(((lane >> 4) << 3) + (lane & 7));
    const unsigned bKof  = (unsigned)(((lane >> 3) & 1) * 16 + wk0 * 2);

    // cp roles: iter i copies row 2i+(lane>>4), seg lane&15
    const int cpr = lane >> 4, cps = lane & 15;

    // xg operands for t=0
    float xa[2][4];
#pragma unroll
    for (int q = 0; q < 2; q++) {
        int e = tid + q * 256, m = e >> 3, du = e & 7;
        const size_t base = (size_t)m * G4 + u0 + du;
        xa[q][0] = g_xg[base];          xa[q][1] = g_xg[base + UU];
        xa[q][2] = g_xg[base + 2 * UU]; xa[q][3] = g_xg[base + 3 * UU];
    }

    for (int t = 0; t < TT; t++) {
        const __half* __restrict__ hc = g_hh[t & 1];
        __half*       __restrict__ hn = g_hh[(t + 1) & 1];

        // ---- stage own h k-slice (64 rows x 128 fp16), own cp.async group ----
#pragma unroll
        for (int i = 0; i < 32; i++) {
            int row = 2 * i + cpr;
            cp16(AwB + (unsigned)(row * (A_STRIDE * 2) + cps * 16),
                 hc + (size_t)row * UU + wk0 + cps * 8);
        }
        asm volatile("cp.async.commit_group;");

        float acc[4][4][4];
#pragma unroll
        for (int a = 0; a < 4; a++)
#pragma unroll
            for (int b = 0; b < 4; b++)
#pragma unroll
                for (int cidx = 0; cidx < 4; cidx++) acc[a][b][cidx] = 0.0f;

        asm volatile("cp.async.wait_group 0;");
        __syncwarp();

        // ---- mma over this warp's K=128 slice: M64 x N32 ----
#pragma unroll
        for (int ks = 0; ks < 8; ks++) {
            uint4 B0 = ldsm4(WtB + bRow * (WT_STRIDE * 2) + bKof + ks * 32);
            uint4 B1 = ldsm4(WtB + (16u + bRow) * (WT_STRIDE * 2) + bKof + ks * 32);
#pragma unroll
            for (int mt = 0; mt < 4; mt++) {
                uint4 Af = ldsm4(AwB + (unsigned)(mt * 16 * (A_STRIDE * 2)) + aLane + ks * 32);
                mma16(acc[mt][0], Af.x, Af.y, Af.z, Af.w, B0.x, B0.y);
                mma16(acc[mt][1], Af.x, Af.y, Af.z, Af.w, B0.z, B0.w);
                mma16(acc[mt][2], Af.x, Af.y, Af.z, Af.w, B1.x, B1.y);
                mma16(acc[mt][3], Af.x, Af.y, Af.z, Af.w, B1.z, B1.w);
            }
        }

        // ---- store partials over own (dead) A slice ----
        {
            float* P = Pal + warp * A_SLICE_F;
#pragma unroll
            for (int mt = 0; mt < 4; mt++)
#pragma unroll
                for (int j = 0; j < 4; j++) {
                    int nb = j * 8 + 2 * lc, r0 = mt * 16 + lr;
                    P[r0 * P_STRIDE + nb]           = acc[mt][j][0];
                    P[r0 * P_STRIDE + nb + 1]       = acc[mt][j][1];
                    P[(r0 + 8) * P_STRIDE + nb]     = acc[mt][j][2];
                    P[(r0 + 8) * P_STRIDE + nb + 1] = acc[mt][j][3];
                }
        }
        __syncthreads();

        // ---- fused 8-way reduction + LSTM cell ----
#pragma unroll
        for (int q = 0; q < 2; q++) {
            int e = tid + q * 256, m = e >> 3, du = e & 7;
            float s0 = 0.f, s1 = 0.f, s2 = 0.f, s3 = 0.f;
#pragma unroll
            for (int w = 0; w < 8; w++) {
                const float* Q = Pal + w * A_SLICE_F + m * P_STRIDE;
                s0 += Q[du];      s1 += Q[8 + du];
                s2 += Q[16 + du]; s3 += Q[24 + du];
            }
            float gi = sigmoidf_(s0 + xa[q][0]);
            float gf = sigmoidf_(s1 + xa[q][1]);
            float gg = tanhf    (s2 + xa[q][2]);
            float go = sigmoidf_(s3 + xa[q][3]);
            float cv = gf * Cl[e] + gi * gg;
            Cl[e] = cv;
            float hv = go * tanhf(cv);
            hn[m * UU + u0 + du] = __float2half_rn(hv);
            if (t == TT - 1) out[m * UU + u0 + du] = hv;
        }
        __syncthreads();                 // hn writes + partial reads done

        // ---- tree barrier: arrive, prefetch xg[t+1], wait ----
        unsigned gen = 0;
        if (tid == 0) bar_arrive(bid, gen);
        if (t + 1 < TT) {
            const size_t tb = (size_t)(t + 1) * BB * G4;
#pragma unroll
            for (int q = 0; q < 2; q++) {
                int e = tid + q * 256, m = e >> 3, du = e & 7;
                const size_t base = tb + (size_t)m * G4 + u0 + du;
                xa[q][0] = g_xg[base];          xa[q][1] = g_xg[base + UU];
                xa[q][2] = g_xg[base + 2 * UU]; xa[q][3] = g_xg[base + 3 * UU];
            }
        }
        if (tid == 0) bar_wait(gen);
        __syncthreads();
    }
}

// ============================================================================
extern "C" void kernel_launch(void* const* d_in, const int* in_sizes, int n_in,
                              void* d_out, int out_size)
{
    const float* x  = (const float*)d_in[0];
    const float* h0 = (const float*)d_in[1];
    const float* c0 = (const float*)d_in[2];
    const float* Wx = (const float*)d_in[3];
    const float* Wh = (const float*)d_in[4];
    const float* b  = (const float*)d_in[5];
    float* out = (float*)d_out;

    conv_x<<<4096, 256>>>(x);
    xg_kernel<<<1024, 256>>>(Wx, b);

    cudaFuncSetAttribute(lstm_persist, cudaFuncAttributeMaxDynamicSharedMemorySize,
                         SMEM_BYTES);
    lstm_persist<<<NCTA, 256, SMEM_BYTES>>>(Wh, h0, c0, out);

    (void)in_sizes; (void)n_in; (void)out_size;
}